// round 14
// baseline (speedup 1.0000x reference)
#include <cuda_runtime.h>
#include <cuda_bf16.h>
#include <cstdint>
#include <cstddef>

// ---------------------------------------------------------------------------
// HighwayLayerDiscrete — persistent HMMA kernel, v10.
// v8 skeleton (full per-layer barrier — v9's fine-grained flags REGRESSED and
// are reverted) with three overlap fixes:
//  1. barrier polling by warps 14-15 runs CONCURRENTLY with the epilogue
//     (warps 0-1); release happens right after epilogue stores via a
//     64-thread named barrier.
//  2. weight region L1-prefetched at layer entry (overlaps with A/MMA).
//  3. out[] store deferred past the flag release; initial y published by
//     hw_init (no startup barrier).
// 128 CTAs = 64 col-slices x 2 row-halves; 16 warps = 2 m-tiles x 8 k-eighths.
// 3-term hi/lo bf16 split; frag-native global layouts; D-frag == next A-frag.
// ---------------------------------------------------------------------------

#define NCTA  128
#define UNITS 1024
#define EMBED 512
#define BATCH 64
#define SEQ   256
#define ALPHA 0.2f

// ---- static global scratch ----
__device__ uint4 g_wy [64*64*2*32];
__device__ uint4 g_wh0[64*64*2*32];
__device__ uint4 g_wh1[64*64*2*32];
__device__ uint4 g_wo [64*64*2*32];
__device__ uint4 g_wx [64*32*2*32];
__device__ uint4 g_y2[2][64*4*2*32];     // y, double-buffered by step parity
__device__ uint4 g_A0 [64*4*2*32];
__device__ uint4 g_A1 [64*4*2*32];
__device__ uint4 g_A2 [64*4*2*32];
__device__ float4 g_projx[(size_t)256*64*4*2*32];   // 64 MB
__device__ unsigned g_flags[NCTA*32];    // one epoch flag per CTA, 128B-spaced

// ---------------- helpers ----------------
__device__ __forceinline__ void pksplit(float a, float b, uint32_t& hi, uint32_t& lo){
    __nv_bfloat162 H, L;
    H.x = __float2bfloat16_rn(a); H.y = __float2bfloat16_rn(b);
    L.x = __float2bfloat16_rn(a - __bfloat162float(H.x));
    L.y = __float2bfloat16_rn(b - __bfloat162float(H.y));
    hi = reinterpret_cast<uint32_t&>(H);
    lo = reinterpret_cast<uint32_t&>(L);
}
__device__ __forceinline__ void mma16816(float d[4], const uint4& a, uint32_t b0, uint32_t b1){
    asm("mma.sync.aligned.m16n8k16.row.col.f32.bf16.bf16.f32 "
        "{%0,%1,%2,%3}, {%4,%5,%6,%7}, {%8,%9}, {%0,%1,%2,%3};"
        : "+f"(d[0]), "+f"(d[1]), "+f"(d[2]), "+f"(d[3])
        : "r"(a.x), "r"(a.y), "r"(a.z), "r"(a.w), "r"(b0), "r"(b1));
}
__device__ __forceinline__ unsigned ld_acq(const unsigned* p){
    unsigned v;
    asm volatile("ld.acquire.gpu.global.u32 %0, [%1];" : "=r"(v) : "l"(p) : "memory");
    return v;
}
__device__ __forceinline__ void st_rel(unsigned* p, unsigned v){
    asm volatile("st.release.gpu.global.u32 [%0], %1;" :: "l"(p), "r"(v) : "memory");
}
#define BAR_SYNC(id, cnt)   asm volatile("bar.sync %0, %1;" :: "r"(id), "r"(cnt) : "memory")

// ---------------- prologue: pack weights into B-frag hi/lo ----------------
__device__ __forceinline__ void pack_w(const float* __restrict__ W, uint4* __restrict__ G,
                                       int sl, int kt, int lane, int nkt){
    int t2 = (lane & 3) * 2, g = lane >> 2, k0 = kt * 16;
    uint32_t h[4], l[4];
    #pragma unroll
    for (int nt = 0; nt < 2; nt++){
        int n = sl*16 + nt*8 + g;
        float e0 = __ldg(&W[(size_t)(k0+t2  )*UNITS + n]);
        float e1 = __ldg(&W[(size_t)(k0+t2+1)*UNITS + n]);
        float e2 = __ldg(&W[(size_t)(k0+t2+8)*UNITS + n]);
        float e3 = __ldg(&W[(size_t)(k0+t2+9)*UNITS + n]);
        pksplit(e0, e1, h[nt*2],   l[nt*2]);
        pksplit(e2, e3, h[nt*2+1], l[nt*2+1]);
    }
    size_t base = ((size_t)(sl*nkt + kt)*2)*32 + lane;
    G[base]      = make_uint4(h[0], h[1], h[2], h[3]);
    G[base + 32] = make_uint4(l[0], l[1], l[2], l[3]);
}

__global__ void hw_split(const float* __restrict__ wy, const float* __restrict__ wx,
                         const float* __restrict__ wh, const float* __restrict__ wo){
    int b = blockIdx.x, tid = threadIdx.x;
    if (b < 2048){
        long id = (long)b*256 + tid;
        int m = (int)(id >> 17);
        int r = (int)(id & 131071);
        const float* W = (m==0) ? wy : (m==1) ? wh : (m==2) ? wh + 1024*1024 : wo;
        uint4* G       = (m==0) ? g_wy : (m==1) ? g_wh0 : (m==2) ? g_wh1 : g_wo;
        int sl = r >> 11, kt = (r >> 5) & 63, lane = r & 31;
        pack_w(W, G, sl, kt, lane, 64);
    } else {
        int r = (b - 2048)*256 + tid;
        int sl = r >> 10, kt = (r >> 5) & 31, lane = r & 31;
        pack_w(wx, g_wx, sl, kt, lane, 32);
    }
}

// ---------------- prologue: flags + initial y (A-frag layout) ----------------
__global__ void hw_init(const float* __restrict__ h0){
    int i = blockIdx.x*256 + threadIdx.x;            // 64 x 256 = 16384
    if (i < NCTA*32) g_flags[i] = 0u;
    int lane = i & 31, split = (i >> 5) & 1, kt = i >> 8;
    int t2 = (lane & 3)*2, k0 = kt*16;
    float a0 = __ldg(&h0[k0+t2]),   a1 = __ldg(&h0[k0+t2+1]);
    float a2 = __ldg(&h0[k0+t2+8]), a3 = __ldg(&h0[k0+t2+9]);
    uint32_t h01, l01, h23, l23;
    pksplit(a0, a1, h01, l01);
    pksplit(a2, a3, h23, l23);
    g_y2[0][i] = split == 0 ? make_uint4(h01, h01, h23, h23)
                            : make_uint4(l01, l01, l23, l23);
}

// ---------------- prologue: proj_x[t] = emb[x[:,t]] * Wx ----------------
__global__ void __launch_bounds__(256, 1)
hw_projx(const int* __restrict__ x, const float* __restrict__ emb){
    extern __shared__ uint4 sA[];              // 128 KB
    __shared__ int sidx[BATCH];
    int t = blockIdx.x >> 4, sg = blockIdx.x & 15;
    int tid = threadIdx.x, w = tid >> 5, lane = tid & 31;

    if (tid < BATCH) sidx[tid] = __ldg(&x[tid*SEQ + t]);
    __syncthreads();

    for (int it = 0; it < 16; it++){
        int item = it*256 + tid;
        int kt = item >> 7, m = (item >> 5) & 3, ln = item & 31;
        int t2 = (ln & 3)*2, g = ln >> 2;
        int r0 = m*16 + g, r1 = r0 + 8;
        const float* e0p = emb + (size_t)sidx[r0]*EMBED + kt*16;
        const float* e1p = emb + (size_t)sidx[r1]*EMBED + kt*16;
        float2 p00 = *(const float2*)(e0p + t2);
        float2 p01 = *(const float2*)(e0p + t2 + 8);
        float2 p10 = *(const float2*)(e1p + t2);
        float2 p11 = *(const float2*)(e1p + t2 + 8);
        uint4 FH, FL;
        pksplit(p00.x, p00.y, FH.x, FL.x);
        pksplit(p10.x, p10.y, FH.y, FL.y);
        pksplit(p01.x, p01.y, FH.z, FL.z);
        pksplit(p11.x, p11.y, FH.w, FL.w);
        sA[((kt*4 + m)*2 + 0)*32 + ln] = FH;
        sA[((kt*4 + m)*2 + 1)*32 + ln] = FL;
    }
    __syncthreads();

    int m = w & 3, kh = w >> 2;
    float acc[4][2][4];
    #pragma unroll
    for (int sl = 0; sl < 4; sl++)
        #pragma unroll
        for (int nt = 0; nt < 2; nt++)
            #pragma unroll
            for (int j = 0; j < 4; j++) acc[sl][nt][j] = 0.f;

    for (int i = 0; i < 16; i++){
        int kt = kh*16 + i;
        uint4 Ahi = sA[((kt*4 + m)*2 + 0)*32 + lane];
        uint4 Alo = sA[((kt*4 + m)*2 + 1)*32 + lane];
        #pragma unroll
        for (int sl = 0; sl < 4; sl++){
            int slice = sg*4 + sl;
            const uint4* bp = &g_wx[((size_t)(slice*32 + kt)*2)*32 + lane];
            uint4 Bhi = __ldg(bp);
            uint4 Blo = __ldg(bp + 32);
            mma16816(acc[sl][0], Ahi, Bhi.x, Bhi.y);
            mma16816(acc[sl][0], Ahi, Blo.x, Blo.y);
            mma16816(acc[sl][0], Alo, Bhi.x, Bhi.y);
            mma16816(acc[sl][1], Ahi, Bhi.z, Bhi.w);
            mma16816(acc[sl][1], Ahi, Blo.z, Blo.w);
            mma16816(acc[sl][1], Alo, Bhi.z, Bhi.w);
        }
    }
    __syncthreads();
    float4* red = (float4*)sA;
    if (kh == 1){
        #pragma unroll
        for (int sl = 0; sl < 4; sl++)
            #pragma unroll
            for (int nt = 0; nt < 2; nt++)
                red[(m*32 + lane)*8 + sl*2 + nt] =
                    make_float4(acc[sl][nt][0], acc[sl][nt][1], acc[sl][nt][2], acc[sl][nt][3]);
    }
    __syncthreads();
    if (kh == 0){
        #pragma unroll
        for (int sl = 0; sl < 4; sl++){
            int slice = sg*4 + sl;
            #pragma unroll
            for (int nt = 0; nt < 2; nt++){
                float4 r = red[(m*32 + lane)*8 + sl*2 + nt];
                g_projx[((((size_t)t*64 + slice)*4 + m)*2 + nt)*32 + lane] =
                    make_float4(acc[sl][nt][0] + r.x, acc[sl][nt][1] + r.y,
                                acc[sl][nt][2] + r.z, acc[sl][nt][3] + r.w);
            }
        }
    }
}

// ---------------- main persistent kernel (128 CTAs x 512 threads) ----------
// MODE 0: +projx, lrelu.  MODE 1: lrelu.  MODE 2: residual y, write out.
// Per layer: MMA -> sync -> { warps 0-1: reduce+epilogue+release |
//                             warps 14-15: poll all 64 CTA flags } -> sync.
template<int MODE>
__device__ __forceinline__ void do_layer(
    int slice, int m, int lm, int kq, int lane, int mh, int tid,
    const uint4* __restrict__ actin, const uint4* __restrict__ wmat,
    uint4* __restrict__ actout, const float* __restrict__ bias16,
    float4* sred, float yacc[2][4], float* __restrict__ out, int t, unsigned e)
{
    const uint4* wb = wmat + (size_t)slice*(64*2*32) + kq*(8*64);

    // L1-prefetch this warp's 8 KB weight region (overlaps with A loads)
    {
        const char* pb = (const char*)wb;
        asm volatile("prefetch.global.L1 [%0];" :: "l"(pb + lane*128));
        asm volatile("prefetch.global.L1 [%0];" :: "l"(pb + (lane+32)*128));
    }
    float4 px0, px1;
    if (MODE == 0 && kq == 0){
        const float4* pp = &g_projx[((((size_t)t*64 + slice)*4 + m)*2)*32 + lane];
        px0 = __ldcg(pp);
        px1 = __ldcg(pp + 32);
    }

    float acc[2][4];
    #pragma unroll
    for (int nt = 0; nt < 2; nt++)
        #pragma unroll
        for (int j = 0; j < 4; j++) acc[nt][j] = 0.f;

    #pragma unroll 8
    for (int i = 0; i < 8; i++){
        int kt = kq*8 + i;
        const uint4* ap = actin + ((kt*4 + m)*2)*32 + lane;
        uint4 Ahi = __ldcg(ap);
        uint4 Alo = __ldcg(ap + 32);
        const uint4* bp = wb + i*64 + lane;
        uint4 Bhi = __ldg(bp);
        uint4 Blo = __ldg(bp + 32);
        mma16816(acc[0], Ahi, Bhi.x, Bhi.y);
        mma16816(acc[0], Ahi, Blo.x, Blo.y);
        mma16816(acc[0], Alo, Bhi.x, Bhi.y);
        mma16816(acc[1], Ahi, Bhi.z, Bhi.w);
        mma16816(acc[1], Ahi, Blo.z, Blo.w);
        mma16816(acc[1], Alo, Bhi.z, Bhi.w);
    }
    if (kq > 0){
        sred[((kq-1)*2 + lm)*64 + lane*2 + 0] =
            make_float4(acc[0][0], acc[0][1], acc[0][2], acc[0][3]);
        sred[((kq-1)*2 + lm)*64 + lane*2 + 1] =
            make_float4(acc[1][0], acc[1][1], acc[1][2], acc[1][3]);
    }
    __syncthreads();                       // partials ready; A fully consumed

    if (kq == 0){
        // ---- epilogue (warps 0-1) ----
        #pragma unroll
        for (int p = 0; p < 7; p++){
            float4 r0 = sred[(p*2 + lm)*64 + lane*2 + 0];
            float4 r1 = sred[(p*2 + lm)*64 + lane*2 + 1];
            acc[0][0] += r0.x; acc[0][1] += r0.y; acc[0][2] += r0.z; acc[0][3] += r0.w;
            acc[1][0] += r1.x; acc[1][1] += r1.y; acc[1][2] += r1.z; acc[1][3] += r1.w;
        }
        int t2 = (lane & 3)*2;
        #pragma unroll
        for (int nt = 0; nt < 2; nt++){
            float b0 = bias16[nt*8 + t2], b1 = bias16[nt*8 + t2 + 1];
            acc[nt][0] += b0; acc[nt][1] += b1; acc[nt][2] += b0; acc[nt][3] += b1;
        }
        if (MODE == 0){
            acc[0][0] += px0.x; acc[0][1] += px0.y; acc[0][2] += px0.z; acc[0][3] += px0.w;
            acc[1][0] += px1.x; acc[1][1] += px1.y; acc[1][2] += px1.z; acc[1][3] += px1.w;
        }
        float v[2][4];
        if (MODE <= 1){
            #pragma unroll
            for (int nt = 0; nt < 2; nt++)
                #pragma unroll
                for (int j = 0; j < 4; j++){
                    float s = acc[nt][j];
                    v[nt][j] = s > 0.f ? s : ALPHA*s;
                }
        } else {
            #pragma unroll
            for (int nt = 0; nt < 2; nt++)
                #pragma unroll
                for (int j = 0; j < 4; j++){
                    yacc[nt][j] += acc[nt][j];
                    v[nt][j] = yacc[nt][j];
                }
        }
        uint4 FH, FL;
        pksplit(v[0][0], v[0][1], FH.x, FL.x);
        pksplit(v[0][2], v[0][3], FH.y, FL.y);
        pksplit(v[1][0], v[1][1], FH.z, FL.z);
        pksplit(v[1][2], v[1][3], FH.w, FL.w);
        uint4* op = actout + ((slice*4 + m)*2)*32 + lane;
        __stcg(op, FH);
        __stcg(op + 32, FL);

        BAR_SYNC(1, 64);                   // both epilogue warps' stores done
        if (lm == 0 && lane == 0)
            st_rel(&g_flags[(mh*64 + slice)*32], e);

        if (MODE == 2){                    // deferred: off the release path
            int g = lane >> 2;
            int b0r = m*16 + g;
            #pragma unroll
            for (int nt = 0; nt < 2; nt++){
                int u = slice*16 + nt*8 + t2;
                __stcg((float2*)&out[(size_t)b0r*(SEQ*UNITS) + (size_t)t*UNITS + u],
                       make_float2(v[nt][0], v[nt][1]));
                __stcg((float2*)&out[(size_t)(b0r+8)*(SEQ*UNITS) + (size_t)t*UNITS + u],
                       make_float2(v[nt][2], v[nt][3]));
            }
        }
    } else if (kq == 7){
        // ---- poll warps (14-15): observe all 64 CTAs, concurrent w/ epilogue
        const unsigned* f = &g_flags[(mh*64 + (lm*32 + lane))*32];
        while (ld_acq(f) < e) { }
    }
    __syncthreads();                       // layer chip-done + epilogue done
}

__global__ void __launch_bounds__(512, 1)
hw_main(const float* __restrict__ bin, const float* __restrict__ bh,
        const float* __restrict__ bo, const float* __restrict__ h0,
        float* __restrict__ out)
{
    __shared__ float4 sred[7*2*64];        // 7 partials x 2 mtiles x 64
    __shared__ float sbias[4][16];
    int cta = blockIdx.x, tid = threadIdx.x, w = tid >> 5, lane = tid & 31;
    int slice = cta & 63, mh = cta >> 6;
    int lm = w & 1, kq = w >> 1;
    int m = mh*2 + lm;
    int t2 = (lane & 3)*2;

    if (tid < 64){
        int l = tid >> 4, c = tid & 15;
        float v = (l==0) ? __ldg(&bin[slice*16 + c])
                : (l==1) ? __ldg(&bh[slice*16 + c])
                : (l==2) ? __ldg(&bh[1024 + slice*16 + c])
                         : __ldg(&bo[slice*16 + c]);
        sbias[l][c] = v;
    }

    float yacc[2][4];
    if (kq == 0){
        #pragma unroll
        for (int nt = 0; nt < 2; nt++){
            int n = slice*16 + nt*8 + t2;
            float v0 = __ldg(&h0[n]), v1 = __ldg(&h0[n+1]);
            yacc[nt][0] = v0; yacc[nt][1] = v1; yacc[nt][2] = v0; yacc[nt][3] = v1;
        }
    }
    __syncthreads();

    for (int t = 0; t < SEQ; t++){
        unsigned e = (unsigned)(t*4);
        do_layer<0>(slice, m, lm, kq, lane, mh, tid, g_y2[t & 1], g_wy,  g_A0,
                    sbias[0], sred, yacc, out, t, e + 1u);
        do_layer<1>(slice, m, lm, kq, lane, mh, tid, g_A0, g_wh0, g_A1,
                    sbias[1], sred, yacc, out, t, e + 2u);
        do_layer<1>(slice, m, lm, kq, lane, mh, tid, g_A1, g_wh1, g_A2,
                    sbias[2], sred, yacc, out, t, e + 3u);
        do_layer<2>(slice, m, lm, kq, lane, mh, tid, g_A2, g_wo,  g_y2[(t + 1) & 1],
                    sbias[3], sred, yacc, out, t, e + 4u);
    }
}

extern "C" void kernel_launch(void* const* d_in, const int* in_sizes, int n_in,
                              void* d_out, int out_size){
    const int*   x   = (const int*)  d_in[0];
    const float* emb = (const float*)d_in[1];
    const float* wy  = (const float*)d_in[2];
    const float* wx  = (const float*)d_in[3];
    const float* bin = (const float*)d_in[4];
    const float* wh  = (const float*)d_in[5];
    const float* bh  = (const float*)d_in[6];
    const float* wo  = (const float*)d_in[7];
    const float* bo  = (const float*)d_in[8];
    const float* h0  = (const float*)d_in[9];
    float* out = (float*)d_out;

    cudaFuncSetAttribute(hw_projx, cudaFuncAttributeMaxDynamicSharedMemorySize, 131072);

    hw_split<<<2304, 256>>>(wy, wx, wh, wo);
    hw_init<<<64, 256>>>(h0);
    hw_projx<<<4096, 256, 131072>>>(x, emb);
    hw_main<<<NCTA, 512>>>(bin, bh, bo, h0, out);
}

// round 15
// speedup vs baseline: 1.2051x; 1.2051x over previous
#include <cuda_runtime.h>
#include <cuda_bf16.h>
#include <cstdint>
#include <cstddef>

// ---------------------------------------------------------------------------
// HighwayLayerDiscrete — persistent HMMA kernel, v11.
// v10 minus the L1 weight prefetch (the element common to BOTH regressing
// rounds v9/v10; suspected L1-thrash + LSU pressure on the critical path).
// Retained from v10:
//  - barrier polling by warps 14-15 CONCURRENT with the epilogue (warps 0-1);
//    release right after epilogue stores via a 64-thread named barrier.
//  - out[] store deferred past the flag release.
//  - initial y published by hw_init (no startup barrier).
// 128 CTAs = 64 col-slices x 2 row-halves; 16 warps = 2 m-tiles x 8 k-eighths.
// 3-term hi/lo bf16 split; frag-native global layouts; D-frag == next A-frag.
// ---------------------------------------------------------------------------

#define NCTA  128
#define UNITS 1024
#define EMBED 512
#define BATCH 64
#define SEQ   256
#define ALPHA 0.2f

// ---- static global scratch ----
__device__ uint4 g_wy [64*64*2*32];
__device__ uint4 g_wh0[64*64*2*32];
__device__ uint4 g_wh1[64*64*2*32];
__device__ uint4 g_wo [64*64*2*32];
__device__ uint4 g_wx [64*32*2*32];
__device__ uint4 g_y2[2][64*4*2*32];     // y, double-buffered by step parity
__device__ uint4 g_A0 [64*4*2*32];
__device__ uint4 g_A1 [64*4*2*32];
__device__ uint4 g_A2 [64*4*2*32];
__device__ float4 g_projx[(size_t)256*64*4*2*32];   // 64 MB
__device__ unsigned g_flags[NCTA*32];    // one epoch flag per CTA, 128B-spaced

// ---------------- helpers ----------------
__device__ __forceinline__ void pksplit(float a, float b, uint32_t& hi, uint32_t& lo){
    __nv_bfloat162 H, L;
    H.x = __float2bfloat16_rn(a); H.y = __float2bfloat16_rn(b);
    L.x = __float2bfloat16_rn(a - __bfloat162float(H.x));
    L.y = __float2bfloat16_rn(b - __bfloat162float(H.y));
    hi = reinterpret_cast<uint32_t&>(H);
    lo = reinterpret_cast<uint32_t&>(L);
}
__device__ __forceinline__ void mma16816(float d[4], const uint4& a, uint32_t b0, uint32_t b1){
    asm("mma.sync.aligned.m16n8k16.row.col.f32.bf16.bf16.f32 "
        "{%0,%1,%2,%3}, {%4,%5,%6,%7}, {%8,%9}, {%0,%1,%2,%3};"
        : "+f"(d[0]), "+f"(d[1]), "+f"(d[2]), "+f"(d[3])
        : "r"(a.x), "r"(a.y), "r"(a.z), "r"(a.w), "r"(b0), "r"(b1));
}
__device__ __forceinline__ unsigned ld_acq(const unsigned* p){
    unsigned v;
    asm volatile("ld.acquire.gpu.global.u32 %0, [%1];" : "=r"(v) : "l"(p) : "memory");
    return v;
}
__device__ __forceinline__ void st_rel(unsigned* p, unsigned v){
    asm volatile("st.release.gpu.global.u32 [%0], %1;" :: "l"(p), "r"(v) : "memory");
}
#define BAR_SYNC(id, cnt)   asm volatile("bar.sync %0, %1;" :: "r"(id), "r"(cnt) : "memory")

// ---------------- prologue: pack weights into B-frag hi/lo ----------------
__device__ __forceinline__ void pack_w(const float* __restrict__ W, uint4* __restrict__ G,
                                       int sl, int kt, int lane, int nkt){
    int t2 = (lane & 3) * 2, g = lane >> 2, k0 = kt * 16;
    uint32_t h[4], l[4];
    #pragma unroll
    for (int nt = 0; nt < 2; nt++){
        int n = sl*16 + nt*8 + g;
        float e0 = __ldg(&W[(size_t)(k0+t2  )*UNITS + n]);
        float e1 = __ldg(&W[(size_t)(k0+t2+1)*UNITS + n]);
        float e2 = __ldg(&W[(size_t)(k0+t2+8)*UNITS + n]);
        float e3 = __ldg(&W[(size_t)(k0+t2+9)*UNITS + n]);
        pksplit(e0, e1, h[nt*2],   l[nt*2]);
        pksplit(e2, e3, h[nt*2+1], l[nt*2+1]);
    }
    size_t base = ((size_t)(sl*nkt + kt)*2)*32 + lane;
    G[base]      = make_uint4(h[0], h[1], h[2], h[3]);
    G[base + 32] = make_uint4(l[0], l[1], l[2], l[3]);
}

__global__ void hw_split(const float* __restrict__ wy, const float* __restrict__ wx,
                         const float* __restrict__ wh, const float* __restrict__ wo){
    int b = blockIdx.x, tid = threadIdx.x;
    if (b < 2048){
        long id = (long)b*256 + tid;
        int m = (int)(id >> 17);
        int r = (int)(id & 131071);
        const float* W = (m==0) ? wy : (m==1) ? wh : (m==2) ? wh + 1024*1024 : wo;
        uint4* G       = (m==0) ? g_wy : (m==1) ? g_wh0 : (m==2) ? g_wh1 : g_wo;
        int sl = r >> 11, kt = (r >> 5) & 63, lane = r & 31;
        pack_w(W, G, sl, kt, lane, 64);
    } else {
        int r = (b - 2048)*256 + tid;
        int sl = r >> 10, kt = (r >> 5) & 31, lane = r & 31;
        pack_w(wx, g_wx, sl, kt, lane, 32);
    }
}

// ---------------- prologue: flags + initial y (A-frag layout) ----------------
__global__ void hw_init(const float* __restrict__ h0){
    int i = blockIdx.x*256 + threadIdx.x;            // 64 x 256 = 16384
    if (i < NCTA*32) g_flags[i] = 0u;
    int lane = i & 31, split = (i >> 5) & 1, kt = i >> 8;
    int t2 = (lane & 3)*2, k0 = kt*16;
    float a0 = __ldg(&h0[k0+t2]),   a1 = __ldg(&h0[k0+t2+1]);
    float a2 = __ldg(&h0[k0+t2+8]), a3 = __ldg(&h0[k0+t2+9]);
    uint32_t h01, l01, h23, l23;
    pksplit(a0, a1, h01, l01);
    pksplit(a2, a3, h23, l23);
    g_y2[0][i] = split == 0 ? make_uint4(h01, h01, h23, h23)
                            : make_uint4(l01, l01, l23, l23);
}

// ---------------- prologue: proj_x[t] = emb[x[:,t]] * Wx ----------------
__global__ void __launch_bounds__(256, 1)
hw_projx(const int* __restrict__ x, const float* __restrict__ emb){
    extern __shared__ uint4 sA[];              // 128 KB
    __shared__ int sidx[BATCH];
    int t = blockIdx.x >> 4, sg = blockIdx.x & 15;
    int tid = threadIdx.x, w = tid >> 5, lane = tid & 31;

    if (tid < BATCH) sidx[tid] = __ldg(&x[tid*SEQ + t]);
    __syncthreads();

    for (int it = 0; it < 16; it++){
        int item = it*256 + tid;
        int kt = item >> 7, m = (item >> 5) & 3, ln = item & 31;
        int t2 = (ln & 3)*2, g = ln >> 2;
        int r0 = m*16 + g, r1 = r0 + 8;
        const float* e0p = emb + (size_t)sidx[r0]*EMBED + kt*16;
        const float* e1p = emb + (size_t)sidx[r1]*EMBED + kt*16;
        float2 p00 = *(const float2*)(e0p + t2);
        float2 p01 = *(const float2*)(e0p + t2 + 8);
        float2 p10 = *(const float2*)(e1p + t2);
        float2 p11 = *(const float2*)(e1p + t2 + 8);
        uint4 FH, FL;
        pksplit(p00.x, p00.y, FH.x, FL.x);
        pksplit(p10.x, p10.y, FH.y, FL.y);
        pksplit(p01.x, p01.y, FH.z, FL.z);
        pksplit(p11.x, p11.y, FH.w, FL.w);
        sA[((kt*4 + m)*2 + 0)*32 + ln] = FH;
        sA[((kt*4 + m)*2 + 1)*32 + ln] = FL;
    }
    __syncthreads();

    int m = w & 3, kh = w >> 2;
    float acc[4][2][4];
    #pragma unroll
    for (int sl = 0; sl < 4; sl++)
        #pragma unroll
        for (int nt = 0; nt < 2; nt++)
            #pragma unroll
            for (int j = 0; j < 4; j++) acc[sl][nt][j] = 0.f;

    for (int i = 0; i < 16; i++){
        int kt = kh*16 + i;
        uint4 Ahi = sA[((kt*4 + m)*2 + 0)*32 + lane];
        uint4 Alo = sA[((kt*4 + m)*2 + 1)*32 + lane];
        #pragma unroll
        for (int sl = 0; sl < 4; sl++){
            int slice = sg*4 + sl;
            const uint4* bp = &g_wx[((size_t)(slice*32 + kt)*2)*32 + lane];
            uint4 Bhi = __ldg(bp);
            uint4 Blo = __ldg(bp + 32);
            mma16816(acc[sl][0], Ahi, Bhi.x, Bhi.y);
            mma16816(acc[sl][0], Ahi, Blo.x, Blo.y);
            mma16816(acc[sl][0], Alo, Bhi.x, Bhi.y);
            mma16816(acc[sl][1], Ahi, Bhi.z, Bhi.w);
            mma16816(acc[sl][1], Ahi, Blo.z, Blo.w);
            mma16816(acc[sl][1], Alo, Bhi.z, Bhi.w);
        }
    }
    __syncthreads();
    float4* red = (float4*)sA;
    if (kh == 1){
        #pragma unroll
        for (int sl = 0; sl < 4; sl++)
            #pragma unroll
            for (int nt = 0; nt < 2; nt++)
                red[(m*32 + lane)*8 + sl*2 + nt] =
                    make_float4(acc[sl][nt][0], acc[sl][nt][1], acc[sl][nt][2], acc[sl][nt][3]);
    }
    __syncthreads();
    if (kh == 0){
        #pragma unroll
        for (int sl = 0; sl < 4; sl++){
            int slice = sg*4 + sl;
            #pragma unroll
            for (int nt = 0; nt < 2; nt++){
                float4 r = red[(m*32 + lane)*8 + sl*2 + nt];
                g_projx[((((size_t)t*64 + slice)*4 + m)*2 + nt)*32 + lane] =
                    make_float4(acc[sl][nt][0] + r.x, acc[sl][nt][1] + r.y,
                                acc[sl][nt][2] + r.z, acc[sl][nt][3] + r.w);
            }
        }
    }
}

// ---------------- main persistent kernel (128 CTAs x 512 threads) ----------
// MODE 0: +projx, lrelu.  MODE 1: lrelu.  MODE 2: residual y, write out.
// Per layer: MMA -> sync -> { warps 0-1: reduce+epilogue+release |
//                             warps 14-15: poll all 64 CTA flags } -> sync.
template<int MODE>
__device__ __forceinline__ void do_layer(
    int slice, int m, int lm, int kq, int lane, int mh, int tid,
    const uint4* __restrict__ actin, const uint4* __restrict__ wmat,
    uint4* __restrict__ actout, const float* __restrict__ bias16,
    float4* sred, float yacc[2][4], float* __restrict__ out, int t, unsigned e)
{
    const uint4* wb = wmat + (size_t)slice*(64*2*32) + kq*(8*64);

    float4 px0, px1;
    if (MODE == 0 && kq == 0){
        const float4* pp = &g_projx[((((size_t)t*64 + slice)*4 + m)*2)*32 + lane];
        px0 = __ldcg(pp);
        px1 = __ldcg(pp + 32);
    }

    float acc[2][4];
    #pragma unroll
    for (int nt = 0; nt < 2; nt++)
        #pragma unroll
        for (int j = 0; j < 4; j++) acc[nt][j] = 0.f;

    #pragma unroll 8
    for (int i = 0; i < 8; i++){
        int kt = kq*8 + i;
        const uint4* ap = actin + ((kt*4 + m)*2)*32 + lane;
        uint4 Ahi = __ldcg(ap);
        uint4 Alo = __ldcg(ap + 32);
        const uint4* bp = wb + i*64 + lane;
        uint4 Bhi = __ldg(bp);
        uint4 Blo = __ldg(bp + 32);
        mma16816(acc[0], Ahi, Bhi.x, Bhi.y);
        mma16816(acc[0], Ahi, Blo.x, Blo.y);
        mma16816(acc[0], Alo, Bhi.x, Bhi.y);
        mma16816(acc[1], Ahi, Bhi.z, Bhi.w);
        mma16816(acc[1], Ahi, Blo.z, Blo.w);
        mma16816(acc[1], Alo, Bhi.z, Bhi.w);
    }
    if (kq > 0){
        sred[((kq-1)*2 + lm)*64 + lane*2 + 0] =
            make_float4(acc[0][0], acc[0][1], acc[0][2], acc[0][3]);
        sred[((kq-1)*2 + lm)*64 + lane*2 + 1] =
            make_float4(acc[1][0], acc[1][1], acc[1][2], acc[1][3]);
    }
    __syncthreads();                       // partials ready; A fully consumed

    if (kq == 0){
        // ---- epilogue (warps 0-1) ----
        #pragma unroll
        for (int p = 0; p < 7; p++){
            float4 r0 = sred[(p*2 + lm)*64 + lane*2 + 0];
            float4 r1 = sred[(p*2 + lm)*64 + lane*2 + 1];
            acc[0][0] += r0.x; acc[0][1] += r0.y; acc[0][2] += r0.z; acc[0][3] += r0.w;
            acc[1][0] += r1.x; acc[1][1] += r1.y; acc[1][2] += r1.z; acc[1][3] += r1.w;
        }
        int t2 = (lane & 3)*2;
        #pragma unroll
        for (int nt = 0; nt < 2; nt++){
            float b0 = bias16[nt*8 + t2], b1 = bias16[nt*8 + t2 + 1];
            acc[nt][0] += b0; acc[nt][1] += b1; acc[nt][2] += b0; acc[nt][3] += b1;
        }
        if (MODE == 0){
            acc[0][0] += px0.x; acc[0][1] += px0.y; acc[0][2] += px0.z; acc[0][3] += px0.w;
            acc[1][0] += px1.x; acc[1][1] += px1.y; acc[1][2] += px1.z; acc[1][3] += px1.w;
        }
        float v[2][4];
        if (MODE <= 1){
            #pragma unroll
            for (int nt = 0; nt < 2; nt++)
                #pragma unroll
                for (int j = 0; j < 4; j++){
                    float s = acc[nt][j];
                    v[nt][j] = s > 0.f ? s : ALPHA*s;
                }
        } else {
            #pragma unroll
            for (int nt = 0; nt < 2; nt++)
                #pragma unroll
                for (int j = 0; j < 4; j++){
                    yacc[nt][j] += acc[nt][j];
                    v[nt][j] = yacc[nt][j];
                }
        }
        uint4 FH, FL;
        pksplit(v[0][0], v[0][1], FH.x, FL.x);
        pksplit(v[0][2], v[0][3], FH.y, FL.y);
        pksplit(v[1][0], v[1][1], FH.z, FL.z);
        pksplit(v[1][2], v[1][3], FH.w, FL.w);
        uint4* op = actout + ((slice*4 + m)*2)*32 + lane;
        __stcg(op, FH);
        __stcg(op + 32, FL);

        BAR_SYNC(1, 64);                   // both epilogue warps' stores done
        if (lm == 0 && lane == 0)
            st_rel(&g_flags[(mh*64 + slice)*32], e);

        if (MODE == 2){                    // deferred: off the release path
            int g = lane >> 2;
            int b0r = m*16 + g;
            #pragma unroll
            for (int nt = 0; nt < 2; nt++){
                int u = slice*16 + nt*8 + t2;
                __stcg((float2*)&out[(size_t)b0r*(SEQ*UNITS) + (size_t)t*UNITS + u],
                       make_float2(v[nt][0], v[nt][1]));
                __stcg((float2*)&out[(size_t)(b0r+8)*(SEQ*UNITS) + (size_t)t*UNITS + u],
                       make_float2(v[nt][2], v[nt][3]));
            }
        }
    } else if (kq == 7){
        // ---- poll warps (14-15): observe all 64 CTAs, concurrent w/ epilogue
        const unsigned* f = &g_flags[(mh*64 + (lm*32 + lane))*32];
        while (ld_acq(f) < e) { }
    }
    __syncthreads();                       // layer chip-done + epilogue done
}

__global__ void __launch_bounds__(512, 1)
hw_main(const float* __restrict__ bin, const float* __restrict__ bh,
        const float* __restrict__ bo, const float* __restrict__ h0,
        float* __restrict__ out)
{
    __shared__ float4 sred[7*2*64];        // 7 partials x 2 mtiles x 64
    __shared__ float sbias[4][16];
    int cta = blockIdx.x, tid = threadIdx.x, w = tid >> 5, lane = tid & 31;
    int slice = cta & 63, mh = cta >> 6;
    int lm = w & 1, kq = w >> 1;
    int m = mh*2 + lm;
    int t2 = (lane & 3)*2;

    if (tid < 64){
        int l = tid >> 4, c = tid & 15;
        float v = (l==0) ? __ldg(&bin[slice*16 + c])
                : (l==1) ? __ldg(&bh[slice*16 + c])
                : (l==2) ? __ldg(&bh[1024 + slice*16 + c])
                         : __ldg(&bo[slice*16 + c]);
        sbias[l][c] = v;
    }

    float yacc[2][4];
    if (kq == 0){
        #pragma unroll
        for (int nt = 0; nt < 2; nt++){
            int n = slice*16 + nt*8 + t2;
            float v0 = __ldg(&h0[n]), v1 = __ldg(&h0[n+1]);
            yacc[nt][0] = v0; yacc[nt][1] = v1; yacc[nt][2] = v0; yacc[nt][3] = v1;
        }
    }
    __syncthreads();

    for (int t = 0; t < SEQ; t++){
        unsigned e = (unsigned)(t*4);
        do_layer<0>(slice, m, lm, kq, lane, mh, tid, g_y2[t & 1], g_wy,  g_A0,
                    sbias[0], sred, yacc, out, t, e + 1u);
        do_layer<1>(slice, m, lm, kq, lane, mh, tid, g_A0, g_wh0, g_A1,
                    sbias[1], sred, yacc, out, t, e + 2u);
        do_layer<1>(slice, m, lm, kq, lane, mh, tid, g_A1, g_wh1, g_A2,
                    sbias[2], sred, yacc, out, t, e + 3u);
        do_layer<2>(slice, m, lm, kq, lane, mh, tid, g_A2, g_wo,  g_y2[(t + 1) & 1],
                    sbias[3], sred, yacc, out, t, e + 4u);
    }
}

extern "C" void kernel_launch(void* const* d_in, const int* in_sizes, int n_in,
                              void* d_out, int out_size){
    const int*   x   = (const int*)  d_in[0];
    const float* emb = (const float*)d_in[1];
    const float* wy  = (const float*)d_in[2];
    const float* wx  = (const float*)d_in[3];
    const float* bin = (const float*)d_in[4];
    const float* wh  = (const float*)d_in[5];
    const float* bh  = (const float*)d_in[6];
    const float* wo  = (const float*)d_in[7];
    const float* bo  = (const float*)d_in[8];
    const float* h0  = (const float*)d_in[9];
    float* out = (float*)d_out;

    cudaFuncSetAttribute(hw_projx, cudaFuncAttributeMaxDynamicSharedMemorySize, 131072);

    hw_split<<<2304, 256>>>(wy, wx, wh, wo);
    hw_init<<<64, 256>>>(h0);
    hw_projx<<<4096, 256, 131072>>>(x, emb);
    hw_main<<<NCTA, 512>>>(bin, bh, bo, h0, out);
}